// round 4
// baseline (speedup 1.0000x reference)
#include <cuda_runtime.h>
#include <cstdint>

// ---------------- scratch (static device allocations are allowed) ----------
__device__ float g_adj[32 * 256 * 256];        // binary adjacency (diag forced 1)
__device__ float g_inv[32 * 256];              // 1 / rowsum
__device__ float g_G[32 * 4 * 256 * 256];      // features @ Wl + bl

// ---------------- JAX threefry2x32, key = (0, 42) --------------------------
// Partitionable mode (JAX >= 0.5 default), bit_width=32:
//   counts = iota(uint64, size);  (hi, lo) = (counts >> 32, counts & 0xffffffff)
//   (bits1, bits2) = threefry2x32(key, (hi, lo));  bits = bits1 ^ bits2
__device__ __forceinline__ uint32_t rotl32(uint32_t x, int d) {
    return (x << d) | (x >> (32 - d));
}

__device__ __forceinline__ void threefry2x32(uint32_t x0, uint32_t x1,
                                             uint32_t& o0, uint32_t& o1) {
    const uint32_t k0 = 0u, k1 = 42u, k2 = 0x1BD11BF0u;  // 0 ^ 42 ^ 0x1BD11BDA
    x0 += k0; x1 += k1;
#define TF_R(r) { x0 += x1; x1 = rotl32(x1, (r)); x1 ^= x0; }
    TF_R(13) TF_R(15) TF_R(26) TF_R(6)
    x0 += k1; x1 += k2 + 1u;
    TF_R(17) TF_R(29) TF_R(16) TF_R(24)
    x0 += k2; x1 += k0 + 2u;
    TF_R(13) TF_R(15) TF_R(26) TF_R(6)
    x0 += k0; x1 += k1 + 3u;
    TF_R(17) TF_R(29) TF_R(16) TF_R(24)
    x0 += k1; x1 += k2 + 4u;
    TF_R(13) TF_R(15) TF_R(26) TF_R(6)
    x0 += k2; x1 += k0 + 5u;
#undef TF_R
    o0 = x0; o1 = x1;
}

__device__ __forceinline__ uint32_t tf_bits(uint32_t flat_idx) {
    uint32_t o0, o1;
    threefry2x32(0u, flat_idx, o0, o1);
    return o0 ^ o1;   // partitionable 32-bit folding: bits1 ^ bits2
}

__device__ __forceinline__ float gumbel_from_bits(uint32_t bits) {
    // jax.random.uniform: f = bitcast(bits>>9 | 0x3f800000) - 1; u = max(minval, f + minval)
    // ((1.0f - 1e-10f) rounds to 1.0f in fp32, so the scale is exactly 1.)
    float f = __uint_as_float((bits >> 9) | 0x3f800000u) - 1.0f;
    float u = fmaxf(1e-10f, f + 1e-10f);
    return -logf(-logf(u));
}

__device__ __forceinline__ float gelu_exact(float x) {
    return 0.5f * x * (1.0f + erff(x * 0.70710678118654752440f));
}

// ---------------- Kernel 1: corr = fm @ fm^T, MLP, gumbel argmax -> adj ----
// grid (4, 4, 32): 64x64 tile of corr per block, 256 threads, 4x4 per thread.
__global__ void corr_adj_kernel(const float* __restrict__ fm,
                                const float* __restrict__ W1, const float* __restrict__ b1,
                                const float* __restrict__ W2, const float* __restrict__ b2,
                                const float* __restrict__ W3, const float* __restrict__ b3) {
    __shared__ float Ast[64][65];   // transposed: Ast[k][m]
    __shared__ float Bst[64][65];   // transposed: Bst[k][n]
    __shared__ float sW1[16], sb1[16], sW2[128], sb2[8], sW3[16], sb3[2];

    const int tid = threadIdx.x;
    if (tid < 16) { sW1[tid] = W1[tid]; sb1[tid] = b1[tid]; sW3[tid] = W3[tid]; }
    if (tid >= 32 && tid < 160)  sW2[tid - 32]  = W2[tid - 32];
    if (tid >= 160 && tid < 168) sb2[tid - 160] = b2[tid - 160];
    if (tid >= 168 && tid < 170) sb3[tid - 168] = b3[tid - 168];

    const int b  = blockIdx.z;
    const int t0 = blockIdx.x * 64;
    const int s0 = blockIdx.y * 64;
    const float* base = fm + (b << 16);   // fm[b] : [256][256]

    const int tx = tid & 15, ty = tid >> 4;
    const int lcol = tx * 4;

    float acc[4][4] = {};

    for (int kk = 0; kk < 256; kk += 64) {
        __syncthreads();
#pragma unroll
        for (int r = 0; r < 4; r++) {
            int row = ty + 16 * r;
            float4 va = *(const float4*)(base + (s0 + row) * 256 + kk + lcol);
            Ast[lcol + 0][row] = va.x; Ast[lcol + 1][row] = va.y;
            Ast[lcol + 2][row] = va.z; Ast[lcol + 3][row] = va.w;
            float4 vb = *(const float4*)(base + (t0 + row) * 256 + kk + lcol);
            Bst[lcol + 0][row] = vb.x; Bst[lcol + 1][row] = vb.y;
            Bst[lcol + 2][row] = vb.z; Bst[lcol + 3][row] = vb.w;
        }
        __syncthreads();
#pragma unroll 8
        for (int k = 0; k < 64; k++) {
            float ar[4], br[4];
#pragma unroll
            for (int i = 0; i < 4; i++) ar[i] = Ast[k][ty + 16 * i];
#pragma unroll
            for (int j = 0; j < 4; j++) br[j] = Bst[k][tx + 16 * j];
#pragma unroll
            for (int i = 0; i < 4; i++)
#pragma unroll
                for (int j = 0; j < 4; j++)
                    acc[i][j] = fmaf(ar[i], br[j], acc[i][j]);
        }
    }

    // epilogue: per corr entry run the tiny MLP and the gumbel argmax
#pragma unroll
    for (int i = 0; i < 4; i++) {
#pragma unroll
        for (int j = 0; j < 4; j++) {
            int s = s0 + ty + 16 * i;
            int t = t0 + tx + 16 * j;
            float corr = acc[i][j];

            // MLP: 1 -> 16 -> 8 -> 2 (exact-erf GELU)
            float h1[16];
#pragma unroll
            for (int a = 0; a < 16; a++)
                h1[a] = gelu_exact(fmaf(corr, sW1[a], sb1[a]));
            float z0 = sb3[0], z1 = sb3[1];
#pragma unroll
            for (int c = 0; c < 8; c++) {
                float acc2 = sb2[c];
#pragma unroll
                for (int a = 0; a < 16; a++)
                    acc2 = fmaf(h1[a], sW2[a * 8 + c], acc2);
                float h2 = gelu_exact(acc2);
                z0 = fmaf(h2, sW3[c * 2 + 0], z0);
                z1 = fmaf(h2, sW3[c * 2 + 1], z1);
            }

            // gumbel noise for flat elements (b, s*256+t, {0,1}) of a
            // (32, 65536, 2) tensor: flat = b*131072 + (s*256+t)*2 + j.
            uint32_t st  = (uint32_t)(s * 256 + t);
            uint32_t idx = ((uint32_t)b << 17) | (st << 1);
            float g0 = gumbel_from_bits(tf_bits(idx));
            float g1 = gumbel_from_bits(tf_bits(idx + 1u));

            // argmax==0 (first index wins ties) -> adj = 1
            float v = (z0 + g0 >= z1 + g1) ? 1.0f : 0.0f;
            if (s == t) v = 1.0f;  // a + (1-a)*I
            g_adj[(b << 16) + (s << 8) + t] = v;
        }
    }
}

// ---------------- Kernel 2: row sums -> 1/sum ------------------------------
__global__ void rowinv_kernel() {
    int warp = (blockIdx.x * blockDim.x + threadIdx.x) >> 5;  // 0..8191
    int lane = threadIdx.x & 31;
    const float* row = g_adj + warp * 256;
    float s = 0.0f;
#pragma unroll
    for (int t = 0; t < 256; t += 32) s += row[t + lane];
#pragma unroll
    for (int o = 16; o > 0; o >>= 1) s += __shfl_xor_sync(0xffffffffu, s, o);
    if (lane == 0) g_inv[warp] = 1.0f / s;
}

// ---------------- Kernel 3: G = features @ Wl + bl -------------------------
// features viewed as [32768, 256]; grid (2, 256), 128x128 tiles, 8x8/thread.
__global__ void gemm_G_kernel(const float* __restrict__ A,
                              const float* __restrict__ Bm,
                              const float* __restrict__ bl) {
    __shared__ float Ast[8][128];
    __shared__ float Bs[8][128];
    const int tid = threadIdx.x;
    const int tx = tid & 15, ty = tid >> 4;
    const int m0 = blockIdx.y * 128, n0 = blockIdx.x * 128;
    const int lar = tid >> 1, lac = (tid & 1) * 4;
    const int lbr = tid >> 5, lbc = (tid & 31) * 4;

    float acc[8][8] = {};
    const float* Ap = A + (m0 + lar) * 256 + lac;
    const float* Bp = Bm + lbr * 256 + n0 + lbc;

    for (int kk = 0; kk < 256; kk += 8) {
        float4 va = *(const float4*)(Ap + kk);
        float4 vb = *(const float4*)(Bp + kk * 256);
        __syncthreads();
        Ast[lac + 0][lar] = va.x; Ast[lac + 1][lar] = va.y;
        Ast[lac + 2][lar] = va.z; Ast[lac + 3][lar] = va.w;
        *(float4*)&Bs[lbr][lbc] = vb;
        __syncthreads();
#pragma unroll
        for (int k = 0; k < 8; k++) {
            float ar[8], br[8];
#pragma unroll
            for (int i = 0; i < 8; i++) ar[i] = Ast[k][ty + 16 * i];
#pragma unroll
            for (int j = 0; j < 8; j++) br[j] = Bs[k][tx + 16 * j];
#pragma unroll
            for (int i = 0; i < 8; i++)
#pragma unroll
                for (int j = 0; j < 8; j++)
                    acc[i][j] = fmaf(ar[i], br[j], acc[i][j]);
        }
    }

    float blv[8];
#pragma unroll
    for (int j = 0; j < 8; j++) blv[j] = bl[n0 + tx + 16 * j];
#pragma unroll
    for (int i = 0; i < 8; i++)
#pragma unroll
        for (int j = 0; j < 8; j++)
            g_G[(m0 + ty + 16 * i) * 256 + n0 + tx + 16 * j] = acc[i][j] + blv[j];
}

// ---------------- Kernel 4: out = (adj/rowsum) @ G -------------------------
// grid (2, 2, 128): z = b*4 + c; 128x128 tiles of the 256x256 product.
__global__ void gemm_out_kernel(float* __restrict__ out) {
    __shared__ float Ast[8][128];
    __shared__ float Bs[8][128];
    const int tid = threadIdx.x;
    const int tx = tid & 15, ty = tid >> 4;
    const int z = blockIdx.z;
    const int b = z >> 2;
    const int m0 = blockIdx.y * 128, n0 = blockIdx.x * 128;
    const int lar = tid >> 1, lac = (tid & 1) * 4;
    const int lbr = tid >> 5, lbc = (tid & 31) * 4;

    float acc[8][8] = {};
    const float* Ap = g_adj + (b << 16) + (m0 + lar) * 256 + lac;
    const float* Bp = g_G + (z << 16) + lbr * 256 + n0 + lbc;

    for (int kk = 0; kk < 256; kk += 8) {
        float4 va = *(const float4*)(Ap + kk);
        float4 vb = *(const float4*)(Bp + kk * 256);
        __syncthreads();
        Ast[lac + 0][lar] = va.x; Ast[lac + 1][lar] = va.y;
        Ast[lac + 2][lar] = va.z; Ast[lac + 3][lar] = va.w;
        *(float4*)&Bs[lbr][lbc] = vb;
        __syncthreads();
#pragma unroll
        for (int k = 0; k < 8; k++) {
            float ar[8], br[8];
#pragma unroll
            for (int i = 0; i < 8; i++) ar[i] = Ast[k][ty + 16 * i];
#pragma unroll
            for (int j = 0; j < 8; j++) br[j] = Bs[k][tx + 16 * j];
#pragma unroll
            for (int i = 0; i < 8; i++)
#pragma unroll
                for (int j = 0; j < 8; j++)
                    acc[i][j] = fmaf(ar[i], br[j], acc[i][j]);
        }
    }

#pragma unroll
    for (int i = 0; i < 8; i++) {
        int s = m0 + ty + 16 * i;
        float sc = g_inv[(b << 8) + s];
#pragma unroll
        for (int j = 0; j < 8; j++)
            out[(z << 16) + s * 256 + n0 + tx + 16 * j] = acc[i][j] * sc;
    }
}

// ---------------- launch ---------------------------------------------------
extern "C" void kernel_launch(void* const* d_in, const int* in_sizes, int n_in,
                              void* d_out, int out_size) {
    const float* features = (const float*)d_in[0];  // [32,4,256,256]
    const float* fm       = (const float*)d_in[1];  // [32,256,256]
    const float* W1 = (const float*)d_in[2];
    const float* b1 = (const float*)d_in[3];
    const float* W2 = (const float*)d_in[4];
    const float* b2 = (const float*)d_in[5];
    const float* W3 = (const float*)d_in[6];
    const float* b3 = (const float*)d_in[7];
    const float* Wl = (const float*)d_in[8];
    const float* bl = (const float*)d_in[9];
    float* out = (float*)d_out;

    corr_adj_kernel<<<dim3(4, 4, 32), 256>>>(fm, W1, b1, W2, b2, W3, b3);
    rowinv_kernel<<<1024, 256>>>();
    gemm_G_kernel<<<dim3(2, 256), 256>>>(features, Wl, bl);
    gemm_out_kernel<<<dim3(2, 2, 128), 256>>>(out);
}

// round 6
// speedup vs baseline: 1.4286x; 1.4286x over previous
#include <cuda_runtime.h>
#include <cstdint>

// ---------------- scratch (static device allocations are allowed) ----------
__device__ float g_adj[32 * 256 * 256];        // binary adjacency (diag forced 1)
__device__ float g_inv[32 * 256];              // 1 / rowsum
__device__ float g_G[32 * 4 * 256 * 256];      // features @ Wl + bl

// ---------------- JAX threefry2x32, key = (0, 42) --------------------------
// Partitionable mode, bit_width=32: (bits1, bits2) = threefry2x32(key, (0, i));
// bits = bits1 ^ bits2.
__device__ __forceinline__ uint32_t rotl32(uint32_t x, int d) {
    return (x << d) | (x >> (32 - d));
}

__device__ __forceinline__ void threefry2x32(uint32_t x0, uint32_t x1,
                                             uint32_t& o0, uint32_t& o1) {
    const uint32_t k0 = 0u, k1 = 42u, k2 = 0x1BD11BF0u;  // 0 ^ 42 ^ 0x1BD11BDA
    x0 += k0; x1 += k1;
#define TF_R(r) { x0 += x1; x1 = rotl32(x1, (r)); x1 ^= x0; }
    TF_R(13) TF_R(15) TF_R(26) TF_R(6)
    x0 += k1; x1 += k2 + 1u;
    TF_R(17) TF_R(29) TF_R(16) TF_R(24)
    x0 += k2; x1 += k0 + 2u;
    TF_R(13) TF_R(15) TF_R(26) TF_R(6)
    x0 += k0; x1 += k1 + 3u;
    TF_R(17) TF_R(29) TF_R(16) TF_R(24)
    x0 += k1; x1 += k2 + 4u;
    TF_R(13) TF_R(15) TF_R(26) TF_R(6)
    x0 += k2; x1 += k0 + 5u;
#undef TF_R
    o0 = x0; o1 = x1;
}

__device__ __forceinline__ uint32_t tf_bits(uint32_t flat_idx) {
    uint32_t o0, o1;
    threefry2x32(0u, flat_idx, o0, o1);
    return o0 ^ o1;
}

__device__ __forceinline__ float gumbel_from_bits(uint32_t bits) {
    float f = __uint_as_float((bits >> 9) | 0x3f800000u) - 1.0f;
    float u = fmaxf(1e-10f, f + 1e-10f);
    return -logf(-logf(u));
}

__device__ __forceinline__ float gelu_exact(float x) {
    return 0.5f * x * (1.0f + erff(x * 0.70710678118654752440f));
}

// ---------------- tf32 mma helpers -----------------------------------------
__device__ __forceinline__ uint32_t f2tf(float x) {
    uint32_t r;
    asm("cvt.rna.tf32.f32 %0, %1;" : "=r"(r) : "f"(x));
    return r;
}

__device__ __forceinline__ void mma_tf32(float* d, const uint32_t* a, const uint32_t* b) {
    asm("mma.sync.aligned.m16n8k8.row.col.f32.tf32.tf32.f32 "
        "{%0,%1,%2,%3},{%4,%5,%6,%7},{%8,%9},{%0,%1,%2,%3};"
        : "+f"(d[0]), "+f"(d[1]), "+f"(d[2]), "+f"(d[3])
        : "r"(a[0]), "r"(a[1]), "r"(a[2]), "r"(a[3]), "r"(b[0]), "r"(b[1]));
}

// ---------------- Kernel 1: corr = fm @ fm^T, MLP, gumbel argmax -> adj ----
// (fp32 FMA on purpose: argmax flips cost ~1/sqrt(128) rel-err per row.)
__global__ void corr_adj_kernel(const float* __restrict__ fm,
                                const float* __restrict__ W1, const float* __restrict__ b1,
                                const float* __restrict__ W2, const float* __restrict__ b2,
                                const float* __restrict__ W3, const float* __restrict__ b3) {
    __shared__ float Ast[64][65];
    __shared__ float Bst[64][65];
    __shared__ float sW1[16], sb1[16], sW2[128], sb2[8], sW3[16], sb3[2];

    const int tid = threadIdx.x;
    if (tid < 16) { sW1[tid] = W1[tid]; sb1[tid] = b1[tid]; sW3[tid] = W3[tid]; }
    if (tid >= 32 && tid < 160)  sW2[tid - 32]  = W2[tid - 32];
    if (tid >= 160 && tid < 168) sb2[tid - 160] = b2[tid - 160];
    if (tid >= 168 && tid < 170) sb3[tid - 168] = b3[tid - 168];

    const int b  = blockIdx.z;
    const int t0 = blockIdx.x * 64;
    const int s0 = blockIdx.y * 64;
    const float* base = fm + (b << 16);

    const int tx = tid & 15, ty = tid >> 4;
    const int lcol = tx * 4;

    float acc[4][4] = {};

    for (int kk = 0; kk < 256; kk += 64) {
        __syncthreads();
#pragma unroll
        for (int r = 0; r < 4; r++) {
            int row = ty + 16 * r;
            float4 va = *(const float4*)(base + (s0 + row) * 256 + kk + lcol);
            Ast[lcol + 0][row] = va.x; Ast[lcol + 1][row] = va.y;
            Ast[lcol + 2][row] = va.z; Ast[lcol + 3][row] = va.w;
            float4 vb = *(const float4*)(base + (t0 + row) * 256 + kk + lcol);
            Bst[lcol + 0][row] = vb.x; Bst[lcol + 1][row] = vb.y;
            Bst[lcol + 2][row] = vb.z; Bst[lcol + 3][row] = vb.w;
        }
        __syncthreads();
#pragma unroll 8
        for (int k = 0; k < 64; k++) {
            float ar[4], br[4];
#pragma unroll
            for (int i = 0; i < 4; i++) ar[i] = Ast[k][ty + 16 * i];
#pragma unroll
            for (int j = 0; j < 4; j++) br[j] = Bst[k][tx + 16 * j];
#pragma unroll
            for (int i = 0; i < 4; i++)
#pragma unroll
                for (int j = 0; j < 4; j++)
                    acc[i][j] = fmaf(ar[i], br[j], acc[i][j]);
        }
    }

#pragma unroll
    for (int i = 0; i < 4; i++) {
#pragma unroll
        for (int j = 0; j < 4; j++) {
            int s = s0 + ty + 16 * i;
            int t = t0 + tx + 16 * j;
            float corr = acc[i][j];

            float h1[16];
#pragma unroll
            for (int a = 0; a < 16; a++)
                h1[a] = gelu_exact(fmaf(corr, sW1[a], sb1[a]));
            float z0 = sb3[0], z1 = sb3[1];
#pragma unroll
            for (int c = 0; c < 8; c++) {
                float acc2 = sb2[c];
#pragma unroll
                for (int a = 0; a < 16; a++)
                    acc2 = fmaf(h1[a], sW2[a * 8 + c], acc2);
                float h2 = gelu_exact(acc2);
                z0 = fmaf(h2, sW3[c * 2 + 0], z0);
                z1 = fmaf(h2, sW3[c * 2 + 1], z1);
            }

            uint32_t st  = (uint32_t)(s * 256 + t);
            uint32_t idx = ((uint32_t)b << 17) | (st << 1);
            float g0 = gumbel_from_bits(tf_bits(idx));
            float g1 = gumbel_from_bits(tf_bits(idx + 1u));

            float v = (z0 + g0 >= z1 + g1) ? 1.0f : 0.0f;
            if (s == t) v = 1.0f;
            g_adj[(b << 16) + (s << 8) + t] = v;
        }
    }
}

// ---------------- Kernel 2: row sums -> 1/sum ------------------------------
__global__ void rowinv_kernel() {
    int warp = (blockIdx.x * blockDim.x + threadIdx.x) >> 5;
    int lane = threadIdx.x & 31;
    const float* row = g_adj + warp * 256;
    float s = 0.0f;
#pragma unroll
    for (int t = 0; t < 256; t += 32) s += row[t + lane];
#pragma unroll
    for (int o = 16; o > 0; o >>= 1) s += __shfl_xor_sync(0xffffffffu, s, o);
    if (lane == 0) g_inv[warp] = 1.0f / s;
}

// ---------------- tf32 GEMM tiles ------------------------------------------
// 128x128x16 block tile, 256 threads = 8 warps as 2x4; warp tile 64x32,
// 4x4 grid of m16n8k8 MMAs, 2 k-steps per tile iter.
// As[m][k] stride 20 (conflict-free for A-frag), Bs[k][n] stride 136.

// ---------------- Kernel 3: G = features @ Wl + bl (tf32 tensor) -----------
__global__ __launch_bounds__(256) void gemm_G_tf32(const float* __restrict__ A,
                                                   const float* __restrict__ Bm,
                                                   const float* __restrict__ bl) {
    __shared__ uint32_t As[128][20];
    __shared__ uint32_t Bs[16][136];

    const int tid  = threadIdx.x;
    const int lane = tid & 31;
    const int g    = lane >> 2;          // groupID
    const int tg   = lane & 3;           // threadID_in_group
    const int warp = tid >> 5;
    const int wr   = warp >> 2;          // 0..1
    const int wc   = warp & 3;           // 0..3
    const int m0   = blockIdx.y * 128;
    const int n0   = blockIdx.x * 128;

    float acc[4][4][4] = {};

    for (int kk = 0; kk < 256; kk += 16) {
        // stage global loads
        uint4 sa[2], sb[2];
#pragma unroll
        for (int u = 0; u < 2; u++) {
            int fa = tid + u * 256;            // A: 512 float4 = 128 rows x 4 slots
            int am = fa >> 2, as = fa & 3;
            float4 v = *(const float4*)(A + (m0 + am) * 256 + kk + as * 4);
            sa[u] = make_uint4(f2tf(v.x), f2tf(v.y), f2tf(v.z), f2tf(v.w));
            int fb = tid + u * 256;            // B: 512 float4 = 16 rows x 32 slots
            int bk = fb >> 5, bs = fb & 31;
            float4 w = *(const float4*)(Bm + (kk + bk) * 256 + n0 + bs * 4);
            sb[u] = make_uint4(f2tf(w.x), f2tf(w.y), f2tf(w.z), f2tf(w.w));
        }
        __syncthreads();
#pragma unroll
        for (int u = 0; u < 2; u++) {
            int fa = tid + u * 256;
            *(uint4*)&As[fa >> 2][(fa & 3) * 4] = sa[u];
            int fb = tid + u * 256;
            *(uint4*)&Bs[fb >> 5][(fb & 31) * 4] = sb[u];
        }
        __syncthreads();

#pragma unroll
        for (int ks = 0; ks < 16; ks += 8) {
            uint32_t afr[4][4], bfr[4][2];
#pragma unroll
            for (int mi = 0; mi < 4; mi++) {
                int m = wr * 64 + mi * 16 + g;
                afr[mi][0] = As[m][ks + tg];
                afr[mi][1] = As[m + 8][ks + tg];
                afr[mi][2] = As[m][ks + tg + 4];
                afr[mi][3] = As[m + 8][ks + tg + 4];
            }
#pragma unroll
            for (int ni = 0; ni < 4; ni++) {
                int n = wc * 32 + ni * 8 + g;
                bfr[ni][0] = Bs[ks + tg][n];
                bfr[ni][1] = Bs[ks + tg + 4][n];
            }
#pragma unroll
            for (int mi = 0; mi < 4; mi++)
#pragma unroll
                for (int ni = 0; ni < 4; ni++)
                    mma_tf32(acc[mi][ni], afr[mi], bfr[ni]);
        }
        __syncthreads();
    }

    // epilogue: + bl, store to g_G
#pragma unroll
    for (int mi = 0; mi < 4; mi++) {
        int r0 = m0 + wr * 64 + mi * 16 + g;
#pragma unroll
        for (int ni = 0; ni < 4; ni++) {
            int c0 = n0 + wc * 32 + ni * 8 + tg * 2;
            float bl0 = __ldg(bl + c0), bl1 = __ldg(bl + c0 + 1);
            g_G[r0 * 256 + c0]             = acc[mi][ni][0] + bl0;
            g_G[r0 * 256 + c0 + 1]         = acc[mi][ni][1] + bl1;
            g_G[(r0 + 8) * 256 + c0]       = acc[mi][ni][2] + bl0;
            g_G[(r0 + 8) * 256 + c0 + 1]   = acc[mi][ni][3] + bl1;
        }
    }
}

// ---------------- Kernel 4: out = (adj/rowsum) @ G (tf32 tensor) -----------
// adj entries are exactly 0/1 -> exact in tf32; only G carries rounding.
__global__ __launch_bounds__(256) void gemm_out_tf32(float* __restrict__ out) {
    __shared__ uint32_t As[128][20];
    __shared__ uint32_t Bs[16][136];

    const int tid  = threadIdx.x;
    const int lane = tid & 31;
    const int g    = lane >> 2;
    const int tg   = lane & 3;
    const int warp = tid >> 5;
    const int wr   = warp >> 2;
    const int wc   = warp & 3;
    const int z    = blockIdx.z;          // b*4 + c
    const int b    = z >> 2;
    const int m0   = blockIdx.y * 128;
    const int n0   = blockIdx.x * 128;

    const float* A  = g_adj + (b << 16);
    const float* Bm = g_G + (z << 16);

    float acc[4][4][4] = {};

    for (int kk = 0; kk < 256; kk += 16) {
        uint4 sa[2], sb[2];
#pragma unroll
        for (int u = 0; u < 2; u++) {
            int fa = tid + u * 256;
            int am = fa >> 2, as = fa & 3;
            float4 v = *(const float4*)(A + (m0 + am) * 256 + kk + as * 4);
            sa[u] = make_uint4(f2tf(v.x), f2tf(v.y), f2tf(v.z), f2tf(v.w));
            int fb = tid + u * 256;
            int bk = fb >> 5, bs = fb & 31;
            float4 w = *(const float4*)(Bm + (kk + bk) * 256 + n0 + bs * 4);
            sb[u] = make_uint4(f2tf(w.x), f2tf(w.y), f2tf(w.z), f2tf(w.w));
        }
        __syncthreads();
#pragma unroll
        for (int u = 0; u < 2; u++) {
            int fa = tid + u * 256;
            *(uint4*)&As[fa >> 2][(fa & 3) * 4] = sa[u];
            int fb = tid + u * 256;
            *(uint4*)&Bs[fb >> 5][(fb & 31) * 4] = sb[u];
        }
        __syncthreads();

#pragma unroll
        for (int ks = 0; ks < 16; ks += 8) {
            uint32_t afr[4][4], bfr[4][2];
#pragma unroll
            for (int mi = 0; mi < 4; mi++) {
                int m = wr * 64 + mi * 16 + g;
                afr[mi][0] = As[m][ks + tg];
                afr[mi][1] = As[m + 8][ks + tg];
                afr[mi][2] = As[m][ks + tg + 4];
                afr[mi][3] = As[m + 8][ks + tg + 4];
            }
#pragma unroll
            for (int ni = 0; ni < 4; ni++) {
                int n = wc * 32 + ni * 8 + g;
                bfr[ni][0] = Bs[ks + tg][n];
                bfr[ni][1] = Bs[ks + tg + 4][n];
            }
#pragma unroll
            for (int mi = 0; mi < 4; mi++)
#pragma unroll
                for (int ni = 0; ni < 4; ni++)
                    mma_tf32(acc[mi][ni], afr[mi], bfr[ni]);
        }
        __syncthreads();
    }

    // epilogue: scale by 1/rowsum, store
#pragma unroll
    for (int mi = 0; mi < 4; mi++) {
        int r0 = m0 + wr * 64 + mi * 16 + g;
        float sc0 = g_inv[(b << 8) + r0];
        float sc1 = g_inv[(b << 8) + r0 + 8];
#pragma unroll
        for (int ni = 0; ni < 4; ni++) {
            int c0 = n0 + wc * 32 + ni * 8 + tg * 2;
            out[(z << 16) + r0 * 256 + c0]           = acc[mi][ni][0] * sc0;
            out[(z << 16) + r0 * 256 + c0 + 1]       = acc[mi][ni][1] * sc0;
            out[(z << 16) + (r0 + 8) * 256 + c0]     = acc[mi][ni][2] * sc1;
            out[(z << 16) + (r0 + 8) * 256 + c0 + 1] = acc[mi][ni][3] * sc1;
        }
    }
}

// ---------------- launch ---------------------------------------------------
extern "C" void kernel_launch(void* const* d_in, const int* in_sizes, int n_in,
                              void* d_out, int out_size) {
    const float* features = (const float*)d_in[0];  // [32,4,256,256]
    const float* fm       = (const float*)d_in[1];  // [32,256,256]
    const float* W1 = (const float*)d_in[2];
    const float* b1 = (const float*)d_in[3];
    const float* W2 = (const float*)d_in[4];
    const float* b2 = (const float*)d_in[5];
    const float* W3 = (const float*)d_in[6];
    const float* b3 = (const float*)d_in[7];
    const float* Wl = (const float*)d_in[8];
    const float* bl = (const float*)d_in[9];
    float* out = (float*)d_out;

    corr_adj_kernel<<<dim3(4, 4, 32), 256>>>(fm, W1, b1, W2, b2, W3, b3);
    rowinv_kernel<<<1024, 256>>>();
    gemm_G_tf32<<<dim3(2, 256), 256>>>(features, Wl, bl);
    gemm_out_tf32<<<dim3(2, 2, 128), 256>>>(out);
}

// round 7
// speedup vs baseline: 3.1169x; 2.1817x over previous
#include <cuda_runtime.h>
#include <cstdint>

// ---------------- scratch (static device allocations are allowed) ----------
__device__ float g_adj[32 * 256 * 256];        // binary adjacency (diag forced 1)
__device__ float g_inv[32 * 256];              // 1 / rowsum
__device__ float g_G[32 * 4 * 256 * 256];      // features @ Wl + bl

#define TBL 32768
#define CMAX 160.0f
#define TSCALE ((float)TBL / (2.0f * CMAX))
#define GUARD 4e-3f
__device__ float g_dz[TBL + 1];                // z0-z1 as a function of corr

// ---------------- JAX threefry2x32, key = (0, 42) --------------------------
// Partitionable mode, bit_width=32: (bits1, bits2) = threefry2x32(key, (0, i));
// bits = bits1 ^ bits2.
__device__ __forceinline__ uint32_t rotl32(uint32_t x, int d) {
    return (x << d) | (x >> (32 - d));
}

__device__ __forceinline__ void threefry2x32(uint32_t x0, uint32_t x1,
                                             uint32_t& o0, uint32_t& o1) {
    const uint32_t k0 = 0u, k1 = 42u, k2 = 0x1BD11BF0u;  // 0 ^ 42 ^ 0x1BD11BDA
    x0 += k0; x1 += k1;
#define TF_R(r) { x0 += x1; x1 = rotl32(x1, (r)); x1 ^= x0; }
    TF_R(13) TF_R(15) TF_R(26) TF_R(6)
    x0 += k1; x1 += k2 + 1u;
    TF_R(17) TF_R(29) TF_R(16) TF_R(24)
    x0 += k2; x1 += k0 + 2u;
    TF_R(13) TF_R(15) TF_R(26) TF_R(6)
    x0 += k0; x1 += k1 + 3u;
    TF_R(17) TF_R(29) TF_R(16) TF_R(24)
    x0 += k1; x1 += k2 + 4u;
    TF_R(13) TF_R(15) TF_R(26) TF_R(6)
    x0 += k2; x1 += k0 + 5u;
#undef TF_R
    o0 = x0; o1 = x1;
}

__device__ __forceinline__ uint32_t tf_bits(uint32_t flat_idx) {
    uint32_t o0, o1;
    threefry2x32(0u, flat_idx, o0, o1);
    return o0 ^ o1;
}

__device__ __forceinline__ float gumbel_from_bits(uint32_t bits) {
    float f = __uint_as_float((bits >> 9) | 0x3f800000u) - 1.0f;
    float u = fmaxf(1e-10f, f + 1e-10f);
    return -__logf(-__logf(u));
}

__device__ __forceinline__ float gelu_exact(float x) {
    return 0.5f * x * (1.0f + erff(x * 0.70710678118654752440f));
}

// Full MLP 1->16->8->2 (exact erf GELU), returns (z0, z1).
__device__ float2 mlp_z(float corr,
                        const float* W1, const float* b1,
                        const float* W2, const float* b2,
                        const float* W3, const float* b3) {
    float h1[16];
#pragma unroll
    for (int a = 0; a < 16; a++)
        h1[a] = gelu_exact(fmaf(corr, W1[a], b1[a]));
    float z0 = b3[0], z1 = b3[1];
#pragma unroll
    for (int c = 0; c < 8; c++) {
        float acc2 = b2[c];
#pragma unroll
        for (int a = 0; a < 16; a++)
            acc2 = fmaf(h1[a], W2[a * 8 + c], acc2);
        float h2 = gelu_exact(acc2);
        z0 = fmaf(h2, W3[c * 2 + 0], z0);
        z1 = fmaf(h2, W3[c * 2 + 1], z1);
    }
    return make_float2(z0, z1);
}

// Exact decision (used only near the guard band / out of table range).
__device__ __noinline__ float mlp_decide(float corr, float g0, float g1,
                                         const float* W1, const float* b1,
                                         const float* W2, const float* b2,
                                         const float* W3, const float* b3) {
    float2 z = mlp_z(corr, W1, b1, W2, b2, W3, b3);
    return (z.x + g0 >= z.y + g1) ? 1.0f : 0.0f;
}

// ---------------- Kernel 0: build the dz table -----------------------------
__global__ void build_dz_kernel(const float* __restrict__ W1, const float* __restrict__ b1,
                                const float* __restrict__ W2, const float* __restrict__ b2,
                                const float* __restrict__ W3, const float* __restrict__ b3) {
    int i = blockIdx.x * blockDim.x + threadIdx.x;
    if (i > TBL) return;
    float corr = -CMAX + (float)i * (2.0f * CMAX / (float)TBL);
    float2 z = mlp_z(corr, W1, b1, W2, b2, W3, b3);
    g_dz[i] = z.x - z.y;
}

// ---------------- Kernel 1: corr = fm @ fm^T, LUT decision -> adj ----------
// (corr GEMM stays fp32 FMA: argmax flips cost ~1e-4 rel-err each.)
__global__ void corr_adj_kernel(const float* __restrict__ fm,
                                const float* __restrict__ W1, const float* __restrict__ b1,
                                const float* __restrict__ W2, const float* __restrict__ b2,
                                const float* __restrict__ W3, const float* __restrict__ b3) {
    __shared__ float Ast[64][65];
    __shared__ float Bst[64][65];
    __shared__ float sW1[16], sb1[16], sW2[128], sb2[8], sW3[16], sb3[2];

    const int tid = threadIdx.x;
    if (tid < 16) { sW1[tid] = W1[tid]; sb1[tid] = b1[tid]; sW3[tid] = W3[tid]; }
    if (tid >= 32 && tid < 160)  sW2[tid - 32]  = W2[tid - 32];
    if (tid >= 160 && tid < 168) sb2[tid - 160] = b2[tid - 160];
    if (tid >= 168 && tid < 170) sb3[tid - 168] = b3[tid - 168];

    const int b  = blockIdx.z;
    const int t0 = blockIdx.x * 64;
    const int s0 = blockIdx.y * 64;
    const float* base = fm + (b << 16);

    const int tx = tid & 15, ty = tid >> 4;
    const int lcol = tx * 4;

    float acc[4][4] = {};

    for (int kk = 0; kk < 256; kk += 64) {
        __syncthreads();
#pragma unroll
        for (int r = 0; r < 4; r++) {
            int row = ty + 16 * r;
            float4 va = *(const float4*)(base + (s0 + row) * 256 + kk + lcol);
            Ast[lcol + 0][row] = va.x; Ast[lcol + 1][row] = va.y;
            Ast[lcol + 2][row] = va.z; Ast[lcol + 3][row] = va.w;
            float4 vb = *(const float4*)(base + (t0 + row) * 256 + kk + lcol);
            Bst[lcol + 0][row] = vb.x; Bst[lcol + 1][row] = vb.y;
            Bst[lcol + 2][row] = vb.z; Bst[lcol + 3][row] = vb.w;
        }
        __syncthreads();
#pragma unroll 8
        for (int k = 0; k < 64; k++) {
            float ar[4], br[4];
#pragma unroll
            for (int i = 0; i < 4; i++) ar[i] = Ast[k][ty + 16 * i];
#pragma unroll
            for (int j = 0; j < 4; j++) br[j] = Bst[k][tx + 16 * j];
#pragma unroll
            for (int i = 0; i < 4; i++)
#pragma unroll
                for (int j = 0; j < 4; j++)
                    acc[i][j] = fmaf(ar[i], br[j], acc[i][j]);
        }
    }

#pragma unroll
    for (int i = 0; i < 4; i++) {
#pragma unroll
        for (int j = 0; j < 4; j++) {
            int s = s0 + ty + 16 * i;
            int t = t0 + tx + 16 * j;
            float corr = acc[i][j];

            uint32_t st  = (uint32_t)(s * 256 + t);
            uint32_t idx = ((uint32_t)b << 17) | (st << 1);
            float g0 = gumbel_from_bits(tf_bits(idx));
            float g1 = gumbel_from_bits(tf_bits(idx + 1u));
            float gm = g1 - g0;     // decide: dz >= gm

            float v;
            float x = (corr + CMAX) * TSCALE;
            if (x >= 0.0f && x < (float)TBL) {
                float fx = floorf(x);
                int   ix = (int)fx;
                float fr = x - fx;
                float d0 = __ldg(&g_dz[ix]);
                float d1 = __ldg(&g_dz[ix + 1]);
                float dz = fmaf(d1 - d0, fr, d0);
                float m  = dz - gm;
                if (fabsf(m) > GUARD) {
                    v = (m >= 0.0f) ? 1.0f : 0.0f;
                } else {
                    v = mlp_decide(corr, g0, g1, sW1, sb1, sW2, sb2, sW3, sb3);
                }
            } else {
                v = mlp_decide(corr, g0, g1, sW1, sb1, sW2, sb2, sW3, sb3);
            }

            if (s == t) v = 1.0f;
            g_adj[(b << 16) + (s << 8) + t] = v;
        }
    }
}

// ---------------- Kernel 2: row sums -> 1/sum ------------------------------
__global__ void rowinv_kernel() {
    int warp = (blockIdx.x * blockDim.x + threadIdx.x) >> 5;
    int lane = threadIdx.x & 31;
    const float* row = g_adj + warp * 256;
    float s = 0.0f;
#pragma unroll
    for (int t = 0; t < 256; t += 32) s += row[t + lane];
#pragma unroll
    for (int o = 16; o > 0; o >>= 1) s += __shfl_xor_sync(0xffffffffu, s, o);
    if (lane == 0) g_inv[warp] = 1.0f / s;
}

// ---------------- tf32 mma helpers -----------------------------------------
__device__ __forceinline__ uint32_t f2tf(float x) {
    uint32_t r;
    asm("cvt.rna.tf32.f32 %0, %1;" : "=r"(r) : "f"(x));
    return r;
}

__device__ __forceinline__ void mma_tf32(float* d, const uint32_t* a, const uint32_t* b) {
    asm("mma.sync.aligned.m16n8k8.row.col.f32.tf32.tf32.f32 "
        "{%0,%1,%2,%3},{%4,%5,%6,%7},{%8,%9},{%0,%1,%2,%3};"
        : "+f"(d[0]), "+f"(d[1]), "+f"(d[2]), "+f"(d[3])
        : "r"(a[0]), "r"(a[1]), "r"(a[2]), "r"(a[3]), "r"(b[0]), "r"(b[1]));
}

// ---------------- Kernel 3: G = features @ Wl + bl (tf32 tensor) -----------
__global__ __launch_bounds__(256) void gemm_G_tf32(const float* __restrict__ A,
                                                   const float* __restrict__ Bm,
                                                   const float* __restrict__ bl) {
    __shared__ uint32_t As[128][20];
    __shared__ uint32_t Bs[16][136];

    const int tid  = threadIdx.x;
    const int lane = tid & 31;
    const int g    = lane >> 2;          // groupID
    const int tg   = lane & 3;           // threadID_in_group
    const int warp = tid >> 5;
    const int wr   = warp >> 2;          // 0..1
    const int wc   = warp & 3;           // 0..3
    const int m0   = blockIdx.y * 128;
    const int n0   = blockIdx.x * 128;

    float acc[4][4][4] = {};

    for (int kk = 0; kk < 256; kk += 16) {
        uint4 sa[2], sb[2];
#pragma unroll
        for (int u = 0; u < 2; u++) {
            int fa = tid + u * 256;            // A: 512 float4 = 128 rows x 4 slots
            int am = fa >> 2, as = fa & 3;
            float4 v = *(const float4*)(A + (m0 + am) * 256 + kk + as * 4);
            sa[u] = make_uint4(f2tf(v.x), f2tf(v.y), f2tf(v.z), f2tf(v.w));
            int fb = tid + u * 256;            // B: 512 float4 = 16 rows x 32 slots
            int bk = fb >> 5, bs = fb & 31;
            float4 w = *(const float4*)(Bm + (kk + bk) * 256 + n0 + bs * 4);
            sb[u] = make_uint4(f2tf(w.x), f2tf(w.y), f2tf(w.z), f2tf(w.w));
        }
        __syncthreads();
#pragma unroll
        for (int u = 0; u < 2; u++) {
            int fa = tid + u * 256;
            *(uint4*)&As[fa >> 2][(fa & 3) * 4] = sa[u];
            int fb = tid + u * 256;
            *(uint4*)&Bs[fb >> 5][(fb & 31) * 4] = sb[u];
        }
        __syncthreads();

#pragma unroll
        for (int ks = 0; ks < 16; ks += 8) {
            uint32_t afr[4][4], bfr[4][2];
#pragma unroll
            for (int mi = 0; mi < 4; mi++) {
                int m = wr * 64 + mi * 16 + g;
                afr[mi][0] = As[m][ks + tg];
                afr[mi][1] = As[m + 8][ks + tg];
                afr[mi][2] = As[m][ks + tg + 4];
                afr[mi][3] = As[m + 8][ks + tg + 4];
            }
#pragma unroll
            for (int ni = 0; ni < 4; ni++) {
                int n = wc * 32 + ni * 8 + g;
                bfr[ni][0] = Bs[ks + tg][n];
                bfr[ni][1] = Bs[ks + tg + 4][n];
            }
#pragma unroll
            for (int mi = 0; mi < 4; mi++)
#pragma unroll
                for (int ni = 0; ni < 4; ni++)
                    mma_tf32(acc[mi][ni], afr[mi], bfr[ni]);
        }
        __syncthreads();
    }

#pragma unroll
    for (int mi = 0; mi < 4; mi++) {
        int r0 = m0 + wr * 64 + mi * 16 + g;
#pragma unroll
        for (int ni = 0; ni < 4; ni++) {
            int c0 = n0 + wc * 32 + ni * 8 + tg * 2;
            float bl0 = __ldg(bl + c0), bl1 = __ldg(bl + c0 + 1);
            g_G[r0 * 256 + c0]             = acc[mi][ni][0] + bl0;
            g_G[r0 * 256 + c0 + 1]         = acc[mi][ni][1] + bl1;
            g_G[(r0 + 8) * 256 + c0]       = acc[mi][ni][2] + bl0;
            g_G[(r0 + 8) * 256 + c0 + 1]   = acc[mi][ni][3] + bl1;
        }
    }
}

// ---------------- Kernel 4: out = (adj/rowsum) @ G (tf32 tensor) -----------
__global__ __launch_bounds__(256) void gemm_out_tf32(float* __restrict__ out) {
    __shared__ uint32_t As[128][20];
    __shared__ uint32_t Bs[16][136];

    const int tid  = threadIdx.x;
    const int lane = tid & 31;
    const int g    = lane >> 2;
    const int tg   = lane & 3;
    const int warp = tid >> 5;
    const int wr   = warp >> 2;
    const int wc   = warp & 3;
    const int z    = blockIdx.z;          // b*4 + c
    const int b    = z >> 2;
    const int m0   = blockIdx.y * 128;
    const int n0   = blockIdx.x * 128;

    const float* A  = g_adj + (b << 16);
    const float* Bm = g_G + (z << 16);

    float acc[4][4][4] = {};

    for (int kk = 0; kk < 256; kk += 16) {
        uint4 sa[2], sb[2];
#pragma unroll
        for (int u = 0; u < 2; u++) {
            int fa = tid + u * 256;
            int am = fa >> 2, as = fa & 3;
            float4 v = *(const float4*)(A + (m0 + am) * 256 + kk + as * 4);
            sa[u] = make_uint4(f2tf(v.x), f2tf(v.y), f2tf(v.z), f2tf(v.w));
            int fb = tid + u * 256;
            int bk = fb >> 5, bs = fb & 31;
            float4 w = *(const float4*)(Bm + (kk + bk) * 256 + n0 + bs * 4);
            sb[u] = make_uint4(f2tf(w.x), f2tf(w.y), f2tf(w.z), f2tf(w.w));
        }
        __syncthreads();
#pragma unroll
        for (int u = 0; u < 2; u++) {
            int fa = tid + u * 256;
            *(uint4*)&As[fa >> 2][(fa & 3) * 4] = sa[u];
            int fb = tid + u * 256;
            *(uint4*)&Bs[fb >> 5][(fb & 31) * 4] = sb[u];
        }
        __syncthreads();

#pragma unroll
        for (int ks = 0; ks < 16; ks += 8) {
            uint32_t afr[4][4], bfr[4][2];
#pragma unroll
            for (int mi = 0; mi < 4; mi++) {
                int m = wr * 64 + mi * 16 + g;
                afr[mi][0] = As[m][ks + tg];
                afr[mi][1] = As[m + 8][ks + tg];
                afr[mi][2] = As[m][ks + tg + 4];
                afr[mi][3] = As[m + 8][ks + tg + 4];
            }
#pragma unroll
            for (int ni = 0; ni < 4; ni++) {
                int n = wc * 32 + ni * 8 + g;
                bfr[ni][0] = Bs[ks + tg][n];
                bfr[ni][1] = Bs[ks + tg + 4][n];
            }
#pragma unroll
            for (int mi = 0; mi < 4; mi++)
#pragma unroll
                for (int ni = 0; ni < 4; ni++)
                    mma_tf32(acc[mi][ni], afr[mi], bfr[ni]);
        }
        __syncthreads();
    }

#pragma unroll
    for (int mi = 0; mi < 4; mi++) {
        int r0 = m0 + wr * 64 + mi * 16 + g;
        float sc0 = g_inv[(b << 8) + r0];
        float sc1 = g_inv[(b << 8) + r0 + 8];
#pragma unroll
        for (int ni = 0; ni < 4; ni++) {
            int c0 = n0 + wc * 32 + ni * 8 + tg * 2;
            out[(z << 16) + r0 * 256 + c0]           = acc[mi][ni][0] * sc0;
            out[(z << 16) + r0 * 256 + c0 + 1]       = acc[mi][ni][1] * sc0;
            out[(z << 16) + (r0 + 8) * 256 + c0]     = acc[mi][ni][2] * sc1;
            out[(z << 16) + (r0 + 8) * 256 + c0 + 1] = acc[mi][ni][3] * sc1;
        }
    }
}

// ---------------- launch ---------------------------------------------------
extern "C" void kernel_launch(void* const* d_in, const int* in_sizes, int n_in,
                              void* d_out, int out_size) {
    const float* features = (const float*)d_in[0];  // [32,4,256,256]
    const float* fm       = (const float*)d_in[1];  // [32,256,256]
    const float* W1 = (const float*)d_in[2];
    const float* b1 = (const float*)d_in[3];
    const float* W2 = (const float*)d_in[4];
    const float* b2 = (const float*)d_in[5];
    const float* W3 = (const float*)d_in[6];
    const float* b3 = (const float*)d_in[7];
    const float* Wl = (const float*)d_in[8];
    const float* bl = (const float*)d_in[9];
    float* out = (float*)d_out;

    build_dz_kernel<<<(TBL + 256) / 256, 256>>>(W1, b1, W2, b2, W3, b3);
    corr_adj_kernel<<<dim3(4, 4, 32), 256>>>(fm, W1, b1, W2, b2, W3, b3);
    rowinv_kernel<<<1024, 256>>>();
    gemm_G_tf32<<<dim3(2, 256), 256>>>(features, Wl, bl);
    gemm_out_tf32<<<dim3(2, 2, 128), 256>>>(out);
}